// round 5
// baseline (speedup 1.0000x reference)
#include <cuda_runtime.h>
#include <math.h>

#define BB 4
#define NN 2048
#define FD 128
#define MROWS (BB*NN)     // 8192 rows total
#define KTOT (NN+1)       // 2049 prefix positions
#define NCH 128
#define CLEN 16           // NN / NCH

// ---------------- scratch (device globals; no allocation) ----------------
__device__ float g_h1[MROWS*FD];
__device__ float g_h2[MROWS*FD];
__device__ float g_g [MROWS*FD];
__device__ float g_s[MROWS];
__device__ float g_d[MROWS];
__device__ float g_sortedD[MROWS];
__device__ int   g_perm[MROWS];
__device__ float g_expD[MROWS];
__device__ float g_dmax[BB];
__device__ float g_sufE1[BB*KTOT];
__device__ float g_preH [BB*KTOT*FD];
__device__ float g_sufEH[BB*KTOT*FD];
__device__ float g_tot[BB*2*NCH*FD];
__device__ float g_off[BB*2*(NCH+1)*FD];
__device__ int   g_rk[MROWS];
__device__ float g_rE[MROWS];
__device__ float g_rw[MROWS];
__device__ float g_rinv[MROWS];

// ---------------- tf32 helpers ----------------
__device__ __forceinline__ float tf32_rn(float x) {
    unsigned u;
    asm("cvt.rna.tf32.f32 %0, %1;" : "=r"(u) : "f"(x));
    return __uint_as_float(u);
}

__device__ __forceinline__ void mma8(float* d, const float* a, float b0, float b1) {
    asm volatile(
        "mma.sync.aligned.m16n8k8.row.col.f32.tf32.tf32.f32 "
        "{%0,%1,%2,%3},{%4,%5,%6,%7},{%8,%9},{%0,%1,%2,%3};"
        : "+f"(d[0]), "+f"(d[1]), "+f"(d[2]), "+f"(d[3])
        : "r"(__float_as_uint(a[0])), "r"(__float_as_uint(a[1])),
          "r"(__float_as_uint(a[2])), "r"(__float_as_uint(a[3])),
          "r"(__float_as_uint(b0)),  "r"(__float_as_uint(b1)));
}

// ---------------- fused linear (3xTF32 mma) + fused s/d dot in epilogue -----
#define KC 16
__global__ __launch_bounds__(256) void gemm_tf32_kernel(
    const float* __restrict__ Xext, int useG,
    const float* __restrict__ W, const float* __restrict__ bias,
    const float* __restrict__ asrc, const float* __restrict__ adst)
{
    const float* __restrict__ X = useG ? g_g : Xext;
    __shared__ float Ah[128][KC+1], Al[128][KC+1];
    __shared__ float Bh[128][KC+1], Bl[128][KC+1];
    __shared__ float sh_s[2][128], sh_d[2][128];
    int tid = threadIdx.x;
    int wid = tid >> 5, lane = tid & 31;
    int gid = lane >> 2, tig = lane & 3;
    int warp_m = wid & 3;
    int warp_n = wid >> 2;
    int row0 = blockIdx.x * 128;
    int col0 = blockIdx.y * 128;

    float acc[2][8][4];
    #pragma unroll
    for (int mt = 0; mt < 2; mt++)
        #pragma unroll
        for (int nt = 0; nt < 8; nt++)
            #pragma unroll
            for (int q = 0; q < 4; q++) acc[mt][nt][q] = 0.f;

    int lrow = tid >> 2;          // 0..63
    int lq = (tid & 3) * 4;       // 0,4,8,12

    for (int kt = 0; kt < FD; kt += KC) {
        float4 xa = *(const float4*)(X + (row0+lrow   )*FD + kt + lq);
        float4 xb = *(const float4*)(X + (row0+lrow+64)*FD + kt + lq);
        float4 wa = *(const float4*)(W + (col0+lrow   )*FD + kt + lq);
        float4 wb = *(const float4*)(W + (col0+lrow+64)*FD + kt + lq);
        __syncthreads();
        {
            float v[4] = {xa.x, xa.y, xa.z, xa.w};
            #pragma unroll
            for (int c = 0; c < 4; c++) {
                float h = tf32_rn(v[c]);
                Ah[lrow][lq+c] = h; Al[lrow][lq+c] = tf32_rn(v[c] - h);
            }
        }
        {
            float v[4] = {xb.x, xb.y, xb.z, xb.w};
            #pragma unroll
            for (int c = 0; c < 4; c++) {
                float h = tf32_rn(v[c]);
                Ah[lrow+64][lq+c] = h; Al[lrow+64][lq+c] = tf32_rn(v[c] - h);
            }
        }
        {
            float v[4] = {wa.x, wa.y, wa.z, wa.w};
            #pragma unroll
            for (int c = 0; c < 4; c++) {
                float h = tf32_rn(v[c]);
                Bh[lrow][lq+c] = h; Bl[lrow][lq+c] = tf32_rn(v[c] - h);
            }
        }
        {
            float v[4] = {wb.x, wb.y, wb.z, wb.w};
            #pragma unroll
            for (int c = 0; c < 4; c++) {
                float h = tf32_rn(v[c]);
                Bh[lrow+64][lq+c] = h; Bl[lrow+64][lq+c] = tf32_rn(v[c] - h);
            }
        }
        __syncthreads();

        #pragma unroll
        for (int kk = 0; kk < KC; kk += 8) {
            float a_h[2][4], a_l[2][4];
            #pragma unroll
            for (int mt = 0; mt < 2; mt++) {
                int r = warp_m*32 + mt*16;
                a_h[mt][0] = Ah[r+gid  ][kk+tig];   a_h[mt][1] = Ah[r+gid+8][kk+tig];
                a_h[mt][2] = Ah[r+gid  ][kk+tig+4]; a_h[mt][3] = Ah[r+gid+8][kk+tig+4];
                a_l[mt][0] = Al[r+gid  ][kk+tig];   a_l[mt][1] = Al[r+gid+8][kk+tig];
                a_l[mt][2] = Al[r+gid  ][kk+tig+4]; a_l[mt][3] = Al[r+gid+8][kk+tig+4];
            }
            #pragma unroll
            for (int nt = 0; nt < 8; nt++) {
                int cc = warp_n*64 + nt*8 + gid;
                float bh0 = Bh[cc][kk+tig], bh1 = Bh[cc][kk+tig+4];
                float bl0 = Bl[cc][kk+tig], bl1 = Bl[cc][kk+tig+4];
                #pragma unroll
                for (int mt = 0; mt < 2; mt++) {
                    mma8(acc[mt][nt], a_h[mt], bh0, bh1);
                    mma8(acc[mt][nt], a_l[mt], bh0, bh1);
                    mma8(acc[mt][nt], a_h[mt], bl0, bl1);
                }
            }
        }
    }

    float* D = (blockIdx.y == 0) ? g_h1 : g_h2;
    float ps[2][2] = {{0.f,0.f},{0.f,0.f}};
    float pd[2][2] = {{0.f,0.f},{0.f,0.f}};
    #pragma unroll
    for (int mt = 0; mt < 2; mt++) {
        #pragma unroll
        for (int nt = 0; nt < 8; nt++) {
            int col = warp_n*64 + nt*8 + tig*2;
            float bv0 = bias[col0 + col];
            float bv1 = bias[col0 + col + 1];
            float v00 = acc[mt][nt][0]+bv0, v01 = acc[mt][nt][1]+bv1;
            float v10 = acc[mt][nt][2]+bv0, v11 = acc[mt][nt][3]+bv1;
            int r0 = row0 + warp_m*32 + mt*16 + gid;
            *(float2*)(D + r0*FD + col)     = make_float2(v00, v01);
            *(float2*)(D + (r0+8)*FD + col) = make_float2(v10, v11);
            if (blockIdx.y == 0) {
                float a0 = asrc[col], a1 = asrc[col+1];
                float d0 = adst[col], d1 = adst[col+1];
                ps[mt][0] += v00*a0 + v01*a1;  pd[mt][0] += v00*d0 + v01*d1;
                ps[mt][1] += v10*a0 + v11*a1;  pd[mt][1] += v10*d0 + v11*d1;
            }
        }
    }
    if (blockIdx.y == 0) {
        #pragma unroll
        for (int mt = 0; mt < 2; mt++)
            #pragma unroll
            for (int sel = 0; sel < 2; sel++) {
                float sv = ps[mt][sel], dv = pd[mt][sel];
                sv += __shfl_xor_sync(0xffffffffu, sv, 1);
                sv += __shfl_xor_sync(0xffffffffu, sv, 2);
                dv += __shfl_xor_sync(0xffffffffu, dv, 1);
                dv += __shfl_xor_sync(0xffffffffu, dv, 2);
                if (tig == 0) {
                    int lrw = warp_m*32 + mt*16 + sel*8 + gid;
                    sh_s[warp_n][lrw] = sv;
                    sh_d[warp_n][lrw] = dv;
                }
            }
        __syncthreads();
        if (tid < 128) {
            g_s[row0 + tid] = sh_s[0][tid] + sh_s[1][tid];
            g_d[row0 + tid] = sh_d[0][tid] + sh_d[1][tid];
        }
    }
}

// ---------------- brute-force exact rank (replaces bitonic sort) -----------
// rank[i] = #{j : d_j < d_i  or  (d_j == d_i and j < i)}  -> scatter
__global__ __launch_bounds__(256) void rank_kernel()
{
    __shared__ float sh[NN];
    int b = blockIdx.y, tid = threadIdx.x;
    #pragma unroll
    for (int j = tid; j < NN; j += 256) sh[j] = g_d[b*NN + j];
    __syncthreads();
    int i = blockIdx.x * 64 + (tid >> 2);
    int q = tid & 3;
    float di = sh[i];
    int cnt = 0;
    int base = q * 512;
    #pragma unroll 8
    for (int t = 0; t < 512; t++) {
        int j = base + ((t + q*13) & 511);     // stagger to avoid bank conflicts
        float dj = sh[j];
        cnt += (dj < di) || (dj == di && j < i);
    }
    cnt += __shfl_xor_sync(0xffffffffu, cnt, 1);
    cnt += __shfl_xor_sync(0xffffffffu, cnt, 2);
    if (q == 0) {
        g_perm[b*NN + cnt] = i;
        g_sortedD[b*NN + cnt] = di;
    }
}

// ---------------- exp + suffix scan of sorted weights ----------------------
__global__ __launch_bounds__(1024) void scanE_kernel()
{
    __shared__ float sa[NN];
    __shared__ float sb[NN];
    int b = blockIdx.x, tid = threadIdx.x;
    #pragma unroll
    for (int j = tid; j < NN; j += 1024) sa[j] = g_sortedD[b*NN + j];
    __syncthreads();
    float dm = sa[NN-1];                      // ascending -> max at end
    for (int j = tid; j < NN; j += 1024) {
        float e = expf(sa[j] - dm);
        g_expD[b*NN + j] = e;
        sb[NN-1-j] = e;                        // reversed for suffix-as-prefix
    }
    __syncthreads();
    float* cur = sb; float* nxt = sa;
    for (int off = 1; off < NN; off <<= 1) {
        for (int j = tid; j < NN; j += 1024) {
            float v = cur[j];
            if (j >= off) v += cur[j-off];
            nxt[j] = v;
        }
        __syncthreads();
        float* tmp = cur; cur = nxt; nxt = tmp;
    }
    for (int j = tid; j < NN; j += 1024)
        g_sufE1[b*KTOT + j] = cur[NN-1-j];
    if (tid == 0) { g_sufE1[b*KTOT + NN] = 0.f; g_dmax[b] = dm; }
}

// ---------------- chunked vector prefix/suffix scans (both dirs fused) ------
__global__ __launch_bounds__(128) void scan_chunk_kernel()
{
    int ch = blockIdx.x, b = blockIdx.y;
    int f = threadIdx.x;
    int k0 = ch * CLEN;
    __shared__ int   rows[CLEN];
    __shared__ float wv[CLEN];
    if (f < CLEN) {
        rows[f] = g_perm[b*NN + k0 + f];
        wv[f]   = g_expD[b*NN + k0 + f];
    }
    __syncthreads();
    const float* hb = g_h1 + b*NN*FD;
    float v[CLEN];
    #pragma unroll
    for (int j = 0; j < CLEN; j++) v[j] = hb[rows[j]*FD + f];

    float acc = 0.f;
    #pragma unroll
    for (int j = 0; j < CLEN; j++) {
        g_preH[(b*KTOT + k0 + j)*FD + f] = acc;
        acc += v[j];
    }
    g_tot[((b*2+0)*NCH + ch)*FD + f] = acc;

    acc = 0.f;
    #pragma unroll
    for (int j = CLEN-1; j >= 0; j--) {
        acc += wv[j] * v[j];
        g_sufEH[(b*KTOT + k0 + j)*FD + f] = acc;
    }
    g_tot[((b*2+1)*NCH + ch)*FD + f] = acc;
}

// ---------------- fused: chunk-offset scan (blocks 0..7) + per-row scalars --
__global__ __launch_bounds__(128) void offsets_rows_kernel(
    const float* __restrict__ abp, int layer)
{
    int bx = blockIdx.x;
    if (bx < 2*BB) {
        int dir = bx & 1, b = bx >> 1;
        int f = threadIdx.x;
        if (dir == 0) {
            float acc = 0.f;
            #pragma unroll 8
            for (int c = 0; c < NCH; c++) {
                g_off[((b*2+0)*(NCH+1) + c)*FD + f] = acc;
                acc += g_tot[((b*2+0)*NCH + c)*FD + f];
            }
            g_off[((b*2+0)*(NCH+1) + NCH)*FD + f] = acc;
            g_preH[(b*KTOT + NN)*FD + f] = 0.f;
        } else {
            float acc = 0.f;
            #pragma unroll 8
            for (int c = NCH-1; c >= 0; c--) {
                g_off[((b*2+1)*(NCH+1) + c)*FD + f] = acc;
                acc += g_tot[((b*2+1)*NCH + c)*FD + f];
            }
            g_off[((b*2+1)*(NCH+1) + NCH)*FD + f] = 0.f;
            g_sufEH[(b*KTOT + NN)*FD + f] = 0.f;
        }
    } else {
        int row = (bx - 2*BB) * 128 + threadIdx.x;
        int b = row >> 11;
        float c   = g_s[row] + abp[layer];
        float thr = -c;
        const float* sd = g_sortedD + b*NN;
        int lo = 0, hi = NN;
        while (lo < hi) { int mid = (lo+hi) >> 1; if (sd[mid] <= thr) lo = mid+1; else hi = mid; }
        int k = lo;
        float E  = expf(c + g_dmax[b]);
        float di = g_d[row];
        float w  = (di > thr) ? expf(c + di) : 1.0f;
        float den = E * g_sufE1[b*KTOT + k] + (float)k - w;
        g_rk[row]   = k;
        g_rE[row]   = E;
        g_rw[row]   = w;
        g_rinv[row] = 1.0f / den;
    }
}

// ---------------- per-row combine (pure streaming) ---------------------------
// MODE 0: g = BN(relu(o + h2)) -> g_g     MODE 1: out = o + h2 -> d_out
template<int MODE>
__global__ __launch_bounds__(128) void combine_kernel(
    const float* __restrict__ gamma, const float* __restrict__ beta,
    const float* __restrict__ mean,  const float* __restrict__ var,
    float* __restrict__ out)
{
    int row = blockIdx.x;
    int b = row >> 11;
    int i = row & (NN-1);
    int f = threadIdx.x;
    int k      = g_rk[row];
    float E    = g_rE[row];
    float wown = g_rw[row];
    float inv  = g_rinv[row];
    int ch = k >> 4;
    float pre = g_preH [(b*KTOT + k)*FD + f] + g_off[((b*2+0)*(NCH+1) + ch)*FD + f];
    float suf = g_sufEH[(b*KTOT + k)*FD + f] + g_off[((b*2+1)*(NCH+1) + ch)*FD + f];
    float h1v = g_h1[row*FD + f];
    float o = (E*suf + pre - wown*h1v) * inv;
    float h2v = g_h2[row*FD + f];
    if (MODE == 0) {
        float gv = fmaxf(o + h2v, 0.f);
        float invs = rsqrtf(var[i] + 1e-5f);
        gv = (gv - mean[i]) * (invs * gamma[i]) + beta[i];
        g_g[row*FD + f] = gv;
    } else {
        out[row*FD + f] = o + h2v;
    }
}

// ---------------- orchestration ----------------
extern "C" void kernel_launch(void* const* d_in, const int* in_sizes, int n_in,
                              void* d_out, int out_size)
{
    (void)in_sizes; (void)n_in; (void)out_size;
    const float* x     = (const float*)d_in[0];
    const float* W1    = (const float*)d_in[2];
    const float* b1    = (const float*)d_in[3];
    const float* asrc  = (const float*)d_in[4];
    const float* adst  = (const float*)d_in[5];
    const float* ab    = (const float*)d_in[6];
    const float* gamma = (const float*)d_in[7];
    const float* beta  = (const float*)d_in[8];
    const float* mean  = (const float*)d_in[9];
    const float* var   = (const float*)d_in[10];
    float* out = (float*)d_out;

    for (int stage = 0; stage < 2; stage++) {
        int k = stage * 2;
        gemm_tf32_kernel<<<dim3(64, 2), 256>>>(x, stage, W1 + k*FD*FD, b1 + k*FD,
                                               asrc + k*FD, adst + k*FD);
        rank_kernel<<<dim3(NN/64, BB), 256>>>();
        scanE_kernel<<<BB, 1024>>>();
        scan_chunk_kernel<<<dim3(NCH, BB), 128>>>();
        offsets_rows_kernel<<<2*BB + MROWS/128, 128>>>(ab, k);
        if (stage == 0)
            combine_kernel<0><<<MROWS, 128>>>(gamma, beta, mean, var, out);
        else
            combine_kernel<1><<<MROWS, 128>>>(gamma, beta, mean, var, out);
    }
}

// round 7
// speedup vs baseline: 1.0304x; 1.0304x over previous
#include <cuda_runtime.h>
#include <math.h>

#define BB 4
#define NN 2048
#define FD 128
#define MROWS (BB*NN)     // 8192 rows total
#define KTOT (NN+1)       // 2049 prefix positions
#define NCH 128
#define CLEN 16           // NN / NCH

// ---------------- scratch (device globals; no allocation) ----------------
__device__ float g_h1[MROWS*FD];
__device__ float g_h2[MROWS*FD];
__device__ float g_g [MROWS*FD];
__device__ float g_s[MROWS];
__device__ float g_d[MROWS];
__device__ float g_sortedD[MROWS];
__device__ int   g_perm[MROWS];
__device__ float g_expD[MROWS];
__device__ float g_dmax[BB];
__device__ float g_sufE1[BB*KTOT];
__device__ float g_preH [BB*KTOT*FD];
__device__ float g_sufEH[BB*KTOT*FD];
__device__ float g_tot[BB*2*NCH*FD];
__device__ float g_off[BB*2*(NCH+1)*FD];
__device__ int   g_rk[MROWS];
__device__ float g_rE[MROWS];
__device__ float g_rw[MROWS];
__device__ float g_rinv[MROWS];

// ---------------- tf32 helpers ----------------
__device__ __forceinline__ float tf32_rn(float x) {
    unsigned u;
    asm("cvt.rna.tf32.f32 %0, %1;" : "=r"(u) : "f"(x));
    return __uint_as_float(u);
}

__device__ __forceinline__ void mma8(float* d, const float* a, float b0, float b1) {
    asm volatile(
        "mma.sync.aligned.m16n8k8.row.col.f32.tf32.tf32.f32 "
        "{%0,%1,%2,%3},{%4,%5,%6,%7},{%8,%9},{%0,%1,%2,%3};"
        : "+f"(d[0]), "+f"(d[1]), "+f"(d[2]), "+f"(d[3])
        : "r"(__float_as_uint(a[0])), "r"(__float_as_uint(a[1])),
          "r"(__float_as_uint(a[2])), "r"(__float_as_uint(a[3])),
          "r"(__float_as_uint(b0)),  "r"(__float_as_uint(b1)));
}

// ---------------- fused linear (3xTF32 mma) + fused s/d dot in epilogue -----
#define KC 16
__global__ __launch_bounds__(256) void gemm_tf32_kernel(
    const float* __restrict__ Xext, int useG,
    const float* __restrict__ W, const float* __restrict__ bias,
    const float* __restrict__ asrc, const float* __restrict__ adst)
{
    const float* __restrict__ X = useG ? g_g : Xext;
    __shared__ float Ah[128][KC+1], Al[128][KC+1];
    __shared__ float Bh[128][KC+1], Bl[128][KC+1];
    __shared__ float sh_s[2][128], sh_d[2][128];
    int tid = threadIdx.x;
    int wid = tid >> 5, lane = tid & 31;
    int gid = lane >> 2, tig = lane & 3;
    int warp_m = wid & 3;
    int warp_n = wid >> 2;
    int row0 = blockIdx.x * 128;
    int col0 = blockIdx.y * 128;

    float acc[2][8][4];
    #pragma unroll
    for (int mt = 0; mt < 2; mt++)
        #pragma unroll
        for (int nt = 0; nt < 8; nt++)
            #pragma unroll
            for (int q = 0; q < 4; q++) acc[mt][nt][q] = 0.f;

    int lrow = tid >> 2;          // 0..63
    int lq = (tid & 3) * 4;       // 0,4,8,12

    for (int kt = 0; kt < FD; kt += KC) {
        float4 xa = *(const float4*)(X + (row0+lrow   )*FD + kt + lq);
        float4 xb = *(const float4*)(X + (row0+lrow+64)*FD + kt + lq);
        float4 wa = *(const float4*)(W + (col0+lrow   )*FD + kt + lq);
        float4 wb = *(const float4*)(W + (col0+lrow+64)*FD + kt + lq);
        __syncthreads();
        {
            float v[4] = {xa.x, xa.y, xa.z, xa.w};
            #pragma unroll
            for (int c = 0; c < 4; c++) {
                float h = tf32_rn(v[c]);
                Ah[lrow][lq+c] = h; Al[lrow][lq+c] = tf32_rn(v[c] - h);
            }
        }
        {
            float v[4] = {xb.x, xb.y, xb.z, xb.w};
            #pragma unroll
            for (int c = 0; c < 4; c++) {
                float h = tf32_rn(v[c]);
                Ah[lrow+64][lq+c] = h; Al[lrow+64][lq+c] = tf32_rn(v[c] - h);
            }
        }
        {
            float v[4] = {wa.x, wa.y, wa.z, wa.w};
            #pragma unroll
            for (int c = 0; c < 4; c++) {
                float h = tf32_rn(v[c]);
                Bh[lrow][lq+c] = h; Bl[lrow][lq+c] = tf32_rn(v[c] - h);
            }
        }
        {
            float v[4] = {wb.x, wb.y, wb.z, wb.w};
            #pragma unroll
            for (int c = 0; c < 4; c++) {
                float h = tf32_rn(v[c]);
                Bh[lrow+64][lq+c] = h; Bl[lrow+64][lq+c] = tf32_rn(v[c] - h);
            }
        }
        __syncthreads();

        #pragma unroll
        for (int kk = 0; kk < KC; kk += 8) {
            float a_h[2][4], a_l[2][4];
            #pragma unroll
            for (int mt = 0; mt < 2; mt++) {
                int r = warp_m*32 + mt*16;
                a_h[mt][0] = Ah[r+gid  ][kk+tig];   a_h[mt][1] = Ah[r+gid+8][kk+tig];
                a_h[mt][2] = Ah[r+gid  ][kk+tig+4]; a_h[mt][3] = Ah[r+gid+8][kk+tig+4];
                a_l[mt][0] = Al[r+gid  ][kk+tig];   a_l[mt][1] = Al[r+gid+8][kk+tig];
                a_l[mt][2] = Al[r+gid  ][kk+tig+4]; a_l[mt][3] = Al[r+gid+8][kk+tig+4];
            }
            #pragma unroll
            for (int nt = 0; nt < 8; nt++) {
                int cc = warp_n*64 + nt*8 + gid;
                float bh0 = Bh[cc][kk+tig], bh1 = Bh[cc][kk+tig+4];
                float bl0 = Bl[cc][kk+tig], bl1 = Bl[cc][kk+tig+4];
                #pragma unroll
                for (int mt = 0; mt < 2; mt++) {
                    mma8(acc[mt][nt], a_h[mt], bh0, bh1);
                    mma8(acc[mt][nt], a_l[mt], bh0, bh1);
                    mma8(acc[mt][nt], a_h[mt], bl0, bl1);
                }
            }
        }
    }

    float* D = (blockIdx.y == 0) ? g_h1 : g_h2;
    float ps[2][2] = {{0.f,0.f},{0.f,0.f}};
    float pd[2][2] = {{0.f,0.f},{0.f,0.f}};
    #pragma unroll
    for (int mt = 0; mt < 2; mt++) {
        #pragma unroll
        for (int nt = 0; nt < 8; nt++) {
            int col = warp_n*64 + nt*8 + tig*2;
            float bv0 = bias[col0 + col];
            float bv1 = bias[col0 + col + 1];
            float v00 = acc[mt][nt][0]+bv0, v01 = acc[mt][nt][1]+bv1;
            float v10 = acc[mt][nt][2]+bv0, v11 = acc[mt][nt][3]+bv1;
            int r0 = row0 + warp_m*32 + mt*16 + gid;
            *(float2*)(D + r0*FD + col)     = make_float2(v00, v01);
            *(float2*)(D + (r0+8)*FD + col) = make_float2(v10, v11);
            if (blockIdx.y == 0) {
                float a0 = asrc[col], a1 = asrc[col+1];
                float d0 = adst[col], d1 = adst[col+1];
                ps[mt][0] += v00*a0 + v01*a1;  pd[mt][0] += v00*d0 + v01*d1;
                ps[mt][1] += v10*a0 + v11*a1;  pd[mt][1] += v10*d0 + v11*d1;
            }
        }
    }
    if (blockIdx.y == 0) {
        #pragma unroll
        for (int mt = 0; mt < 2; mt++)
            #pragma unroll
            for (int sel = 0; sel < 2; sel++) {
                float sv = ps[mt][sel], dv = pd[mt][sel];
                sv += __shfl_xor_sync(0xffffffffu, sv, 1);
                sv += __shfl_xor_sync(0xffffffffu, sv, 2);
                dv += __shfl_xor_sync(0xffffffffu, dv, 1);
                dv += __shfl_xor_sync(0xffffffffu, dv, 2);
                if (tig == 0) {
                    int lrw = warp_m*32 + mt*16 + sel*8 + gid;
                    sh_s[warp_n][lrw] = sv;
                    sh_d[warp_n][lrw] = dv;
                }
            }
        __syncthreads();
        if (tid < 128) {
            g_s[row0 + tid] = sh_s[0][tid] + sh_s[1][tid];
            g_d[row0 + tid] = sh_d[0][tid] + sh_d[1][tid];
        }
    }
}

// ---------------- brute-force exact rank (replaces bitonic sort) -----------
// rank[i] = #{j : d_j < d_i  or  (d_j == d_i and j < i)}  -> scatter
__global__ __launch_bounds__(256) void rank_kernel()
{
    __shared__ float sh[NN];
    int b = blockIdx.y, tid = threadIdx.x;
    #pragma unroll
    for (int j = tid; j < NN; j += 256) sh[j] = g_d[b*NN + j];
    __syncthreads();
    int i = blockIdx.x * 64 + (tid >> 2);
    int q = tid & 3;
    float di = sh[i];
    int cnt = 0;
    int base = q * 512;
    #pragma unroll 8
    for (int t = 0; t < 512; t++) {
        int j = base + ((t + q*13) & 511);     // stagger to avoid bank conflicts
        float dj = sh[j];
        cnt += (dj < di) || (dj == di && j < i);
    }
    cnt += __shfl_xor_sync(0xffffffffu, cnt, 1);
    cnt += __shfl_xor_sync(0xffffffffu, cnt, 2);
    if (q == 0) {
        g_perm[b*NN + cnt] = i;
        g_sortedD[b*NN + cnt] = di;
    }
}

// ---------------- exp + suffix scan of sorted weights ----------------------
__global__ __launch_bounds__(1024) void scanE_kernel()
{
    __shared__ float sa[NN];
    __shared__ float sb[NN];
    int b = blockIdx.x, tid = threadIdx.x;
    #pragma unroll
    for (int j = tid; j < NN; j += 1024) sa[j] = g_sortedD[b*NN + j];
    __syncthreads();
    float dm = sa[NN-1];                      // ascending -> max at end
    for (int j = tid; j < NN; j += 1024) {
        float e = expf(sa[j] - dm);
        g_expD[b*NN + j] = e;
        sb[NN-1-j] = e;                        // reversed for suffix-as-prefix
    }
    __syncthreads();
    float* cur = sb; float* nxt = sa;
    for (int off = 1; off < NN; off <<= 1) {
        for (int j = tid; j < NN; j += 1024) {
            float v = cur[j];
            if (j >= off) v += cur[j-off];
            nxt[j] = v;
        }
        __syncthreads();
        float* tmp = cur; cur = nxt; nxt = tmp;
    }
    for (int j = tid; j < NN; j += 1024)
        g_sufE1[b*KTOT + j] = cur[NN-1-j];
    if (tid == 0) { g_sufE1[b*KTOT + NN] = 0.f; g_dmax[b] = dm; }
}

// ---------------- chunked vector prefix/suffix scans (both dirs fused) ------
__global__ __launch_bounds__(128) void scan_chunk_kernel()
{
    int ch = blockIdx.x, b = blockIdx.y;
    int f = threadIdx.x;
    int k0 = ch * CLEN;
    __shared__ int   rows[CLEN];
    __shared__ float wv[CLEN];
    if (f < CLEN) {
        rows[f] = g_perm[b*NN + k0 + f];
        wv[f]   = g_expD[b*NN + k0 + f];
    }
    __syncthreads();
    const float* hb = g_h1 + b*NN*FD;
    float v[CLEN];
    #pragma unroll
    for (int j = 0; j < CLEN; j++) v[j] = hb[rows[j]*FD + f];

    float acc = 0.f;
    #pragma unroll
    for (int j = 0; j < CLEN; j++) {
        g_preH[(b*KTOT + k0 + j)*FD + f] = acc;
        acc += v[j];
    }
    g_tot[((b*2+0)*NCH + ch)*FD + f] = acc;

    acc = 0.f;
    #pragma unroll
    for (int j = CLEN-1; j >= 0; j--) {
        acc += wv[j] * v[j];
        g_sufEH[(b*KTOT + k0 + j)*FD + f] = acc;
    }
    g_tot[((b*2+1)*NCH + ch)*FD + f] = acc;
}

// ---------------- fused: chunk-offset scan (blocks 0..7) + per-row scalars --
__global__ __launch_bounds__(128) void offsets_rows_kernel(
    const float* __restrict__ abp, int layer)
{
    int bx = blockIdx.x;
    if (bx < 2*BB) {
        int dir = bx & 1, b = bx >> 1;
        int f = threadIdx.x;
        if (dir == 0) {
            float acc = 0.f;
            #pragma unroll 8
            for (int c = 0; c < NCH; c++) {
                g_off[((b*2+0)*(NCH+1) + c)*FD + f] = acc;
                acc += g_tot[((b*2+0)*NCH + c)*FD + f];
            }
            g_off[((b*2+0)*(NCH+1) + NCH)*FD + f] = acc;
            g_preH[(b*KTOT + NN)*FD + f] = 0.f;
        } else {
            float acc = 0.f;
            #pragma unroll 8
            for (int c = NCH-1; c >= 0; c--) {
                g_off[((b*2+1)*(NCH+1) + c)*FD + f] = acc;
                acc += g_tot[((b*2+1)*NCH + c)*FD + f];
            }
            g_off[((b*2+1)*(NCH+1) + NCH)*FD + f] = 0.f;
            g_sufEH[(b*KTOT + NN)*FD + f] = 0.f;
        }
    } else {
        int row = (bx - 2*BB) * 128 + threadIdx.x;
        int b = row >> 11;
        float c   = g_s[row] + abp[layer];
        float thr = -c;
        const float* sd = g_sortedD + b*NN;
        int lo = 0, hi = NN;
        while (lo < hi) { int mid = (lo+hi) >> 1; if (sd[mid] <= thr) lo = mid+1; else hi = mid; }
        int k = lo;
        float E  = expf(c + g_dmax[b]);
        float di = g_d[row];
        float w  = (di > thr) ? expf(c + di) : 1.0f;
        float den = E * g_sufE1[b*KTOT + k] + (float)k - w;
        g_rk[row]   = k;
        g_rE[row]   = E;
        g_rw[row]   = w;
        g_rinv[row] = 1.0f / den;
    }
}

// ---------------- per-row combine (pure streaming) ---------------------------
// MODE 0: g = BN(relu(o + h2)) -> g_g     MODE 1: out = o + h2 -> d_out
template<int MODE>
__global__ __launch_bounds__(128) void combine_kernel(
    const float* __restrict__ gamma, const float* __restrict__ beta,
    const float* __restrict__ mean,  const float* __restrict__ var,
    float* __restrict__ out)
{
    int row = blockIdx.x;
    int b = row >> 11;
    int i = row & (NN-1);
    int f = threadIdx.x;
    int k      = g_rk[row];
    float E    = g_rE[row];
    float wown = g_rw[row];
    float inv  = g_rinv[row];
    int ch = k >> 4;
    float pre = g_preH [(b*KTOT + k)*FD + f] + g_off[((b*2+0)*(NCH+1) + ch)*FD + f];
    float suf = g_sufEH[(b*KTOT + k)*FD + f] + g_off[((b*2+1)*(NCH+1) + ch)*FD + f];
    float h1v = g_h1[row*FD + f];
    float o = (E*suf + pre - wown*h1v) * inv;
    float h2v = g_h2[row*FD + f];
    if (MODE == 0) {
        float gv = fmaxf(o + h2v, 0.f);
        float invs = rsqrtf(var[i] + 1e-5f);
        gv = (gv - mean[i]) * (invs * gamma[i]) + beta[i];
        g_g[row*FD + f] = gv;
    } else {
        out[row*FD + f] = o + h2v;
    }
}

// ---------------- orchestration ----------------
extern "C" void kernel_launch(void* const* d_in, const int* in_sizes, int n_in,
                              void* d_out, int out_size)
{
    (void)in_sizes; (void)n_in; (void)out_size;
    const float* x     = (const float*)d_in[0];
    const float* W1    = (const float*)d_in[2];
    const float* b1    = (const float*)d_in[3];
    const float* asrc  = (const float*)d_in[4];
    const float* adst  = (const float*)d_in[5];
    const float* ab    = (const float*)d_in[6];
    const float* gamma = (const float*)d_in[7];
    const float* beta  = (const float*)d_in[8];
    const float* mean  = (const float*)d_in[9];
    const float* var   = (const float*)d_in[10];
    float* out = (float*)d_out;

    for (int stage = 0; stage < 2; stage++) {
        int k = stage * 2;
        gemm_tf32_kernel<<<dim3(64, 2), 256>>>(x, stage, W1 + k*FD*FD, b1 + k*FD,
                                               asrc + k*FD, adst + k*FD);
        rank_kernel<<<dim3(NN/64, BB), 256>>>();
        scanE_kernel<<<BB, 1024>>>();
        scan_chunk_kernel<<<dim3(NCH, BB), 128>>>();
        offsets_rows_kernel<<<2*BB + MROWS/128, 128>>>(ab, k);
        if (stage == 0)
            combine_kernel<0><<<MROWS, 128>>>(gamma, beta, mean, var, out);
        else
            combine_kernel<1><<<MROWS, 128>>>(gamma, beta, mean, var, out);
    }
}

// round 9
// speedup vs baseline: 1.0339x; 1.0034x over previous
#include <cuda_runtime.h>
#include <math.h>

#define BB 4
#define NN 2048
#define FD 128
#define MROWS (BB*NN)     // 8192 rows total
#define KTOT (NN+1)       // 2049 prefix positions
#define NCH 128
#define CLEN 16           // NN / NCH

// ---------------- scratch (device globals; no allocation) ----------------
__device__ float g_h1[MROWS*FD];
__device__ float g_h2[MROWS*FD];
__device__ float g_g [MROWS*FD];
__device__ float g_s[MROWS];
__device__ float g_d[MROWS];
__device__ float g_sortedD[MROWS];
__device__ int   g_perm[MROWS];
__device__ float g_expD[MROWS];
__device__ float g_dmax[BB];
__device__ float g_sufE1[BB*KTOT];
__device__ float g_preH [BB*KTOT*FD];
__device__ float g_sufEH[BB*KTOT*FD];
__device__ float g_tot[BB*2*NCH*FD];
__device__ float g_off[BB*2*(NCH+1)*FD];
__device__ int   g_rk[MROWS];
__device__ float g_rE[MROWS];
__device__ float g_rw[MROWS];
__device__ float g_rinv[MROWS];

// ---------------- tf32 helpers ----------------
__device__ __forceinline__ float tf32_rn(float x) {
    unsigned u;
    asm("cvt.rna.tf32.f32 %0, %1;" : "=r"(u) : "f"(x));
    return __uint_as_float(u);
}

__device__ __forceinline__ void mma8(float* d, const float* a, float b0, float b1) {
    asm volatile(
        "mma.sync.aligned.m16n8k8.row.col.f32.tf32.tf32.f32 "
        "{%0,%1,%2,%3},{%4,%5,%6,%7},{%8,%9},{%0,%1,%2,%3};"
        : "+f"(d[0]), "+f"(d[1]), "+f"(d[2]), "+f"(d[3])
        : "r"(__float_as_uint(a[0])), "r"(__float_as_uint(a[1])),
          "r"(__float_as_uint(a[2])), "r"(__float_as_uint(a[3])),
          "r"(__float_as_uint(b0)),  "r"(__float_as_uint(b1)));
}

// ---------------- fused linear (3xTF32 mma) + fused s/d dot in epilogue -----
#define KC 16
__global__ __launch_bounds__(256) void gemm_tf32_kernel(
    const float* __restrict__ Xext, int useG,
    const float* __restrict__ W, const float* __restrict__ bias,
    const float* __restrict__ asrc, const float* __restrict__ adst)
{
    const float* __restrict__ X = useG ? g_g : Xext;
    __shared__ float Ah[128][KC+1], Al[128][KC+1];
    __shared__ float Bh[128][KC+1], Bl[128][KC+1];
    __shared__ float sh_s[2][128], sh_d[2][128];
    int tid = threadIdx.x;
    int wid = tid >> 5, lane = tid & 31;
    int gid = lane >> 2, tig = lane & 3;
    int warp_m = wid & 3;
    int warp_n = wid >> 2;
    int row0 = blockIdx.x * 128;
    int col0 = blockIdx.y * 128;

    float acc[2][8][4];
    #pragma unroll
    for (int mt = 0; mt < 2; mt++)
        #pragma unroll
        for (int nt = 0; nt < 8; nt++)
            #pragma unroll
            for (int q = 0; q < 4; q++) acc[mt][nt][q] = 0.f;

    int lrow = tid >> 2;          // 0..63
    int lq = (tid & 3) * 4;       // 0,4,8,12

    for (int kt = 0; kt < FD; kt += KC) {
        float4 xa = *(const float4*)(X + (row0+lrow   )*FD + kt + lq);
        float4 xb = *(const float4*)(X + (row0+lrow+64)*FD + kt + lq);
        float4 wa = *(const float4*)(W + (col0+lrow   )*FD + kt + lq);
        float4 wb = *(const float4*)(W + (col0+lrow+64)*FD + kt + lq);
        __syncthreads();
        {
            float v[4] = {xa.x, xa.y, xa.z, xa.w};
            #pragma unroll
            for (int c = 0; c < 4; c++) {
                float h = tf32_rn(v[c]);
                Ah[lrow][lq+c] = h; Al[lrow][lq+c] = tf32_rn(v[c] - h);
            }
        }
        {
            float v[4] = {xb.x, xb.y, xb.z, xb.w};
            #pragma unroll
            for (int c = 0; c < 4; c++) {
                float h = tf32_rn(v[c]);
                Ah[lrow+64][lq+c] = h; Al[lrow+64][lq+c] = tf32_rn(v[c] - h);
            }
        }
        {
            float v[4] = {wa.x, wa.y, wa.z, wa.w};
            #pragma unroll
            for (int c = 0; c < 4; c++) {
                float h = tf32_rn(v[c]);
                Bh[lrow][lq+c] = h; Bl[lrow][lq+c] = tf32_rn(v[c] - h);
            }
        }
        {
            float v[4] = {wb.x, wb.y, wb.z, wb.w};
            #pragma unroll
            for (int c = 0; c < 4; c++) {
                float h = tf32_rn(v[c]);
                Bh[lrow+64][lq+c] = h; Bl[lrow+64][lq+c] = tf32_rn(v[c] - h);
            }
        }
        __syncthreads();

        #pragma unroll
        for (int kk = 0; kk < KC; kk += 8) {
            float a_h[2][4], a_l[2][4];
            #pragma unroll
            for (int mt = 0; mt < 2; mt++) {
                int r = warp_m*32 + mt*16;
                a_h[mt][0] = Ah[r+gid  ][kk+tig];   a_h[mt][1] = Ah[r+gid+8][kk+tig];
                a_h[mt][2] = Ah[r+gid  ][kk+tig+4]; a_h[mt][3] = Ah[r+gid+8][kk+tig+4];
                a_l[mt][0] = Al[r+gid  ][kk+tig];   a_l[mt][1] = Al[r+gid+8][kk+tig];
                a_l[mt][2] = Al[r+gid  ][kk+tig+4]; a_l[mt][3] = Al[r+gid+8][kk+tig+4];
            }
            #pragma unroll
            for (int nt = 0; nt < 8; nt++) {
                int cc = warp_n*64 + nt*8 + gid;
                float bh0 = Bh[cc][kk+tig], bh1 = Bh[cc][kk+tig+4];
                float bl0 = Bl[cc][kk+tig], bl1 = Bl[cc][kk+tig+4];
                #pragma unroll
                for (int mt = 0; mt < 2; mt++) {
                    mma8(acc[mt][nt], a_h[mt], bh0, bh1);
                    mma8(acc[mt][nt], a_l[mt], bh0, bh1);
                    mma8(acc[mt][nt], a_h[mt], bl0, bl1);
                }
            }
        }
    }

    float* D = (blockIdx.y == 0) ? g_h1 : g_h2;
    float ps[2][2] = {{0.f,0.f},{0.f,0.f}};
    float pd[2][2] = {{0.f,0.f},{0.f,0.f}};
    #pragma unroll
    for (int mt = 0; mt < 2; mt++) {
        #pragma unroll
        for (int nt = 0; nt < 8; nt++) {
            int col = warp_n*64 + nt*8 + tig*2;
            float bv0 = bias[col0 + col];
            float bv1 = bias[col0 + col + 1];
            float v00 = acc[mt][nt][0]+bv0, v01 = acc[mt][nt][1]+bv1;
            float v10 = acc[mt][nt][2]+bv0, v11 = acc[mt][nt][3]+bv1;
            int r0 = row0 + warp_m*32 + mt*16 + gid;
            *(float2*)(D + r0*FD + col)     = make_float2(v00, v01);
            *(float2*)(D + (r0+8)*FD + col) = make_float2(v10, v11);
            if (blockIdx.y == 0) {
                float a0 = asrc[col], a1 = asrc[col+1];
                float d0 = adst[col], d1 = adst[col+1];
                ps[mt][0] += v00*a0 + v01*a1;  pd[mt][0] += v00*d0 + v01*d1;
                ps[mt][1] += v10*a0 + v11*a1;  pd[mt][1] += v10*d0 + v11*d1;
            }
        }
    }
    if (blockIdx.y == 0) {
        #pragma unroll
        for (int mt = 0; mt < 2; mt++)
            #pragma unroll
            for (int sel = 0; sel < 2; sel++) {
                float sv = ps[mt][sel], dv = pd[mt][sel];
                sv += __shfl_xor_sync(0xffffffffu, sv, 1);
                sv += __shfl_xor_sync(0xffffffffu, sv, 2);
                dv += __shfl_xor_sync(0xffffffffu, dv, 1);
                dv += __shfl_xor_sync(0xffffffffu, dv, 2);
                if (tig == 0) {
                    int lrw = warp_m*32 + mt*16 + sel*8 + gid;
                    sh_s[warp_n][lrw] = sv;
                    sh_d[warp_n][lrw] = dv;
                }
            }
        __syncthreads();
        if (tid < 128) {
            g_s[row0 + tid] = sh_s[0][tid] + sh_s[1][tid];
            g_d[row0 + tid] = sh_d[0][tid] + sh_d[1][tid];
        }
    }
}

// ---------------- brute-force exact rank (replaces bitonic sort) -----------
// rank[i] = #{j : d_j < d_i  or  (d_j == d_i and j < i)}  -> scatter
__global__ __launch_bounds__(256) void rank_kernel()
{
    __shared__ float sh[NN];
    int b = blockIdx.y, tid = threadIdx.x;
    #pragma unroll
    for (int j = tid; j < NN; j += 256) sh[j] = g_d[b*NN + j];
    __syncthreads();
    int i = blockIdx.x * 64 + (tid >> 2);
    int q = tid & 3;
    float di = sh[i];
    int cnt = 0;
    int base = q * 512;
    #pragma unroll 8
    for (int t = 0; t < 512; t++) {
        int j = base + ((t + q*13) & 511);     // stagger to avoid bank conflicts
        float dj = sh[j];
        cnt += (dj < di) || (dj == di && j < i);
    }
    cnt += __shfl_xor_sync(0xffffffffu, cnt, 1);
    cnt += __shfl_xor_sync(0xffffffffu, cnt, 2);
    if (q == 0) {
        g_perm[b*NN + cnt] = i;
        g_sortedD[b*NN + cnt] = di;
    }
}

// ---------------- exp + suffix scan of sorted weights ----------------------
__global__ __launch_bounds__(1024) void scanE_kernel()
{
    __shared__ float sa[NN];
    __shared__ float sb[NN];
    int b = blockIdx.x, tid = threadIdx.x;
    #pragma unroll
    for (int j = tid; j < NN; j += 1024) sa[j] = g_sortedD[b*NN + j];
    __syncthreads();
    float dm = sa[NN-1];                      // ascending -> max at end
    for (int j = tid; j < NN; j += 1024) {
        float e = expf(sa[j] - dm);
        g_expD[b*NN + j] = e;
        sb[NN-1-j] = e;                        // reversed for suffix-as-prefix
    }
    __syncthreads();
    float* cur = sb; float* nxt = sa;
    for (int off = 1; off < NN; off <<= 1) {
        for (int j = tid; j < NN; j += 1024) {
            float v = cur[j];
            if (j >= off) v += cur[j-off];
            nxt[j] = v;
        }
        __syncthreads();
        float* tmp = cur; cur = nxt; nxt = tmp;
    }
    for (int j = tid; j < NN; j += 1024)
        g_sufE1[b*KTOT + j] = cur[NN-1-j];
    if (tid == 0) { g_sufE1[b*KTOT + NN] = 0.f; g_dmax[b] = dm; }
}

// ---------------- chunked vector prefix/suffix scans (both dirs fused) ------
__global__ __launch_bounds__(128) void scan_chunk_kernel()
{
    int ch = blockIdx.x, b = blockIdx.y;
    int f = threadIdx.x;
    int k0 = ch * CLEN;
    __shared__ int   rows[CLEN];
    __shared__ float wv[CLEN];
    if (f < CLEN) {
        rows[f] = g_perm[b*NN + k0 + f];
        wv[f]   = g_expD[b*NN + k0 + f];
    }
    __syncthreads();
    const float* hb = g_h1 + b*NN*FD;
    float v[CLEN];
    #pragma unroll
    for (int j = 0; j < CLEN; j++) v[j] = hb[rows[j]*FD + f];

    float acc = 0.f;
    #pragma unroll
    for (int j = 0; j < CLEN; j++) {
        g_preH[(b*KTOT + k0 + j)*FD + f] = acc;
        acc += v[j];
    }
    g_tot[((b*2+0)*NCH + ch)*FD + f] = acc;

    acc = 0.f;
    #pragma unroll
    for (int j = CLEN-1; j >= 0; j--) {
        acc += wv[j] * v[j];
        g_sufEH[(b*KTOT + k0 + j)*FD + f] = acc;
    }
    g_tot[((b*2+1)*NCH + ch)*FD + f] = acc;
}

// ---------------- fused: chunk-offset scan (blocks 0..7) + per-row scalars --
__global__ __launch_bounds__(128) void offsets_rows_kernel(
    const float* __restrict__ abp, int layer)
{
    int bx = blockIdx.x;
    if (bx < 2*BB) {
        int dir = bx & 1, b = bx >> 1;
        int f = threadIdx.x;
        if (dir == 0) {
            float acc = 0.f;
            #pragma unroll 8
            for (int c = 0; c < NCH; c++) {
                g_off[((b*2+0)*(NCH+1) + c)*FD + f] = acc;
                acc += g_tot[((b*2+0)*NCH + c)*FD + f];
            }
            g_off[((b*2+0)*(NCH+1) + NCH)*FD + f] = acc;
            g_preH[(b*KTOT + NN)*FD + f] = 0.f;
        } else {
            float acc = 0.f;
            #pragma unroll 8
            for (int c = NCH-1; c >= 0; c--) {
                g_off[((b*2+1)*(NCH+1) + c)*FD + f] = acc;
                acc += g_tot[((b*2+1)*NCH + c)*FD + f];
            }
            g_off[((b*2+1)*(NCH+1) + NCH)*FD + f] = 0.f;
            g_sufEH[(b*KTOT + NN)*FD + f] = 0.f;
        }
    } else {
        int row = (bx - 2*BB) * 128 + threadIdx.x;
        int b = row >> 11;
        float c   = g_s[row] + abp[layer];
        float thr = -c;
        const float* sd = g_sortedD + b*NN;
        int lo = 0, hi = NN;
        while (lo < hi) { int mid = (lo+hi) >> 1; if (sd[mid] <= thr) lo = mid+1; else hi = mid; }
        int k = lo;
        float E  = expf(c + g_dmax[b]);
        float di = g_d[row];
        float w  = (di > thr) ? expf(c + di) : 1.0f;
        float den = E * g_sufE1[b*KTOT + k] + (float)k - w;
        g_rk[row]   = k;
        g_rE[row]   = E;
        g_rw[row]   = w;
        g_rinv[row] = 1.0f / den;
    }
}

// ---------------- per-row combine (pure streaming) ---------------------------
// MODE 0: g = BN(relu(o + h2)) -> g_g     MODE 1: out = o + h2 -> d_out
template<int MODE>
__global__ __launch_bounds__(128) void combine_kernel(
    const float* __restrict__ gamma, const float* __restrict__ beta,
    const float* __restrict__ mean,  const float* __restrict__ var,
    float* __restrict__ out)
{
    int row = blockIdx.x;
    int b = row >> 11;
    int i = row & (NN-1);
    int f = threadIdx.x;
    int k      = g_rk[row];
    float E    = g_rE[row];
    float wown = g_rw[row];
    float inv  = g_rinv[row];
    int ch = k >> 4;
    float pre = g_preH [(b*KTOT + k)*FD + f] + g_off[((b*2+0)*(NCH+1) + ch)*FD + f];
    float suf = g_sufEH[(b*KTOT + k)*FD + f] + g_off[((b*2+1)*(NCH+1) + ch)*FD + f];
    float h1v = g_h1[row*FD + f];
    float o = (E*suf + pre - wown*h1v) * inv;
    float h2v = g_h2[row*FD + f];
    if (MODE == 0) {
        float gv = fmaxf(o + h2v, 0.f);
        float invs = rsqrtf(var[i] + 1e-5f);
        gv = (gv - mean[i]) * (invs * gamma[i]) + beta[i];
        g_g[row*FD + f] = gv;
    } else {
        out[row*FD + f] = o + h2v;
    }
}

// ---------------- orchestration ----------------
extern "C" void kernel_launch(void* const* d_in, const int* in_sizes, int n_in,
                              void* d_out, int out_size)
{
    (void)in_sizes; (void)n_in; (void)out_size;
    const float* x     = (const float*)d_in[0];
    const float* W1    = (const float*)d_in[2];
    const float* b1    = (const float*)d_in[3];
    const float* asrc  = (const float*)d_in[4];
    const float* adst  = (const float*)d_in[5];
    const float* ab    = (const float*)d_in[6];
    const float* gamma = (const float*)d_in[7];
    const float* beta  = (const float*)d_in[8];
    const float* mean  = (const float*)d_in[9];
    const float* var   = (const float*)d_in[10];
    float* out = (float*)d_out;

    for (int stage = 0; stage < 2; stage++) {
        int k = stage * 2;
        gemm_tf32_kernel<<<dim3(64, 2), 256>>>(x, stage, W1 + k*FD*FD, b1 + k*FD,
                                               asrc + k*FD, adst + k*FD);
        rank_kernel<<<dim3(NN/64, BB), 256>>>();
        scanE_kernel<<<BB, 1024>>>();
        scan_chunk_kernel<<<dim3(NCH, BB), 128>>>();
        offsets_rows_kernel<<<2*BB + MROWS/128, 128>>>(ab, k);
        if (stage == 0)
            combine_kernel<0><<<MROWS, 128>>>(gamma, beta, mean, var, out);
        else
            combine_kernel<1><<<MROWS, 128>>>(gamma, beta, mean, var, out);
    }
}

// round 10
// speedup vs baseline: 1.0444x; 1.0102x over previous
#include <cuda_runtime.h>
#include <math.h>

#define BB 4
#define NN 2048
#define FD 128
#define MROWS (BB*NN)     // 8192 rows total
#define KTOT (NN+1)       // 2049 prefix positions
#define NCH 128
#define CLEN 16           // NN / NCH

// ---------------- scratch (device globals; no allocation) ----------------
__device__ float g_h1[MROWS*FD];
__device__ float g_h2[MROWS*FD];
__device__ float g_g [MROWS*FD];
__device__ float g_s[MROWS];
__device__ float g_d[MROWS];
__device__ float g_sortedD[MROWS];
__device__ int   g_perm[MROWS];
__device__ float g_expD[MROWS];
__device__ float g_dmax[BB];
__device__ float g_sufE1[BB*KTOT];
__device__ float g_preH [BB*KTOT*FD];
__device__ float g_sufEH[BB*KTOT*FD];
__device__ float g_tot[BB*2*NCH*FD];
__device__ float g_off[BB*2*(NCH+1)*FD];
__device__ int   g_rk[MROWS];
__device__ float g_rE[MROWS];
__device__ float g_rw[MROWS];
__device__ float g_rinv[MROWS];

// ---------------- tf32 helpers ----------------
__device__ __forceinline__ float tf32_rn(float x) {
    unsigned u;
    asm("cvt.rna.tf32.f32 %0, %1;" : "=r"(u) : "f"(x));
    return __uint_as_float(u);
}

__device__ __forceinline__ void mma8(float* d, const float* a, float b0, float b1) {
    asm volatile(
        "mma.sync.aligned.m16n8k8.row.col.f32.tf32.tf32.f32 "
        "{%0,%1,%2,%3},{%4,%5,%6,%7},{%8,%9},{%0,%1,%2,%3};"
        : "+f"(d[0]), "+f"(d[1]), "+f"(d[2]), "+f"(d[3])
        : "r"(__float_as_uint(a[0])), "r"(__float_as_uint(a[1])),
          "r"(__float_as_uint(a[2])), "r"(__float_as_uint(a[3])),
          "r"(__float_as_uint(b0)),  "r"(__float_as_uint(b1)));
}

// ---------------- fused linear (3xTF32 mma) + fused s/d dot in epilogue -----
#define KC 16
__global__ __launch_bounds__(256) void gemm_tf32_kernel(
    const float* __restrict__ Xext, int useG,
    const float* __restrict__ W, const float* __restrict__ bias,
    const float* __restrict__ asrc, const float* __restrict__ adst)
{
    const float* __restrict__ X = useG ? g_g : Xext;
    __shared__ float Ah[128][KC+1], Al[128][KC+1];
    __shared__ float Bh[128][KC+1], Bl[128][KC+1];
    __shared__ float sh_s[2][128], sh_d[2][128];
    int tid = threadIdx.x;
    int wid = tid >> 5, lane = tid & 31;
    int gid = lane >> 2, tig = lane & 3;
    int warp_m = wid & 3;
    int warp_n = wid >> 2;
    int row0 = blockIdx.x * 128;
    int col0 = blockIdx.y * 128;

    float acc[2][8][4];
    #pragma unroll
    for (int mt = 0; mt < 2; mt++)
        #pragma unroll
        for (int nt = 0; nt < 8; nt++)
            #pragma unroll
            for (int q = 0; q < 4; q++) acc[mt][nt][q] = 0.f;

    int lrow = tid >> 2;          // 0..63
    int lq = (tid & 3) * 4;       // 0,4,8,12

    for (int kt = 0; kt < FD; kt += KC) {
        float4 xa = *(const float4*)(X + (row0+lrow   )*FD + kt + lq);
        float4 xb = *(const float4*)(X + (row0+lrow+64)*FD + kt + lq);
        float4 wa = *(const float4*)(W + (col0+lrow   )*FD + kt + lq);
        float4 wb = *(const float4*)(W + (col0+lrow+64)*FD + kt + lq);
        __syncthreads();
        {
            float v[4] = {xa.x, xa.y, xa.z, xa.w};
            #pragma unroll
            for (int c = 0; c < 4; c++) {
                float h = tf32_rn(v[c]);
                Ah[lrow][lq+c] = h; Al[lrow][lq+c] = tf32_rn(v[c] - h);
            }
        }
        {
            float v[4] = {xb.x, xb.y, xb.z, xb.w};
            #pragma unroll
            for (int c = 0; c < 4; c++) {
                float h = tf32_rn(v[c]);
                Ah[lrow+64][lq+c] = h; Al[lrow+64][lq+c] = tf32_rn(v[c] - h);
            }
        }
        {
            float v[4] = {wa.x, wa.y, wa.z, wa.w};
            #pragma unroll
            for (int c = 0; c < 4; c++) {
                float h = tf32_rn(v[c]);
                Bh[lrow][lq+c] = h; Bl[lrow][lq+c] = tf32_rn(v[c] - h);
            }
        }
        {
            float v[4] = {wb.x, wb.y, wb.z, wb.w};
            #pragma unroll
            for (int c = 0; c < 4; c++) {
                float h = tf32_rn(v[c]);
                Bh[lrow+64][lq+c] = h; Bl[lrow+64][lq+c] = tf32_rn(v[c] - h);
            }
        }
        __syncthreads();

        #pragma unroll
        for (int kk = 0; kk < KC; kk += 8) {
            float a_h[2][4], a_l[2][4];
            #pragma unroll
            for (int mt = 0; mt < 2; mt++) {
                int r = warp_m*32 + mt*16;
                a_h[mt][0] = Ah[r+gid  ][kk+tig];   a_h[mt][1] = Ah[r+gid+8][kk+tig];
                a_h[mt][2] = Ah[r+gid  ][kk+tig+4]; a_h[mt][3] = Ah[r+gid+8][kk+tig+4];
                a_l[mt][0] = Al[r+gid  ][kk+tig];   a_l[mt][1] = Al[r+gid+8][kk+tig];
                a_l[mt][2] = Al[r+gid  ][kk+tig+4]; a_l[mt][3] = Al[r+gid+8][kk+tig+4];
            }
            #pragma unroll
            for (int nt = 0; nt < 8; nt++) {
                int cc = warp_n*64 + nt*8 + gid;
                float bh0 = Bh[cc][kk+tig], bh1 = Bh[cc][kk+tig+4];
                float bl0 = Bl[cc][kk+tig], bl1 = Bl[cc][kk+tig+4];
                #pragma unroll
                for (int mt = 0; mt < 2; mt++) {
                    mma8(acc[mt][nt], a_h[mt], bh0, bh1);
                    mma8(acc[mt][nt], a_l[mt], bh0, bh1);
                    mma8(acc[mt][nt], a_h[mt], bl0, bl1);
                }
            }
        }
    }

    float* D = (blockIdx.y == 0) ? g_h1 : g_h2;
    float ps[2][2] = {{0.f,0.f},{0.f,0.f}};
    float pd[2][2] = {{0.f,0.f},{0.f,0.f}};
    #pragma unroll
    for (int mt = 0; mt < 2; mt++) {
        #pragma unroll
        for (int nt = 0; nt < 8; nt++) {
            int col = warp_n*64 + nt*8 + tig*2;
            float bv0 = bias[col0 + col];
            float bv1 = bias[col0 + col + 1];
            float v00 = acc[mt][nt][0]+bv0, v01 = acc[mt][nt][1]+bv1;
            float v10 = acc[mt][nt][2]+bv0, v11 = acc[mt][nt][3]+bv1;
            int r0 = row0 + warp_m*32 + mt*16 + gid;
            *(float2*)(D + r0*FD + col)     = make_float2(v00, v01);
            *(float2*)(D + (r0+8)*FD + col) = make_float2(v10, v11);
            if (blockIdx.y == 0) {
                float a0 = asrc[col], a1 = asrc[col+1];
                float d0 = adst[col], d1 = adst[col+1];
                ps[mt][0] += v00*a0 + v01*a1;  pd[mt][0] += v00*d0 + v01*d1;
                ps[mt][1] += v10*a0 + v11*a1;  pd[mt][1] += v10*d0 + v11*d1;
            }
        }
    }
    if (blockIdx.y == 0) {
        #pragma unroll
        for (int mt = 0; mt < 2; mt++)
            #pragma unroll
            for (int sel = 0; sel < 2; sel++) {
                float sv = ps[mt][sel], dv = pd[mt][sel];
                sv += __shfl_xor_sync(0xffffffffu, sv, 1);
                sv += __shfl_xor_sync(0xffffffffu, sv, 2);
                dv += __shfl_xor_sync(0xffffffffu, dv, 1);
                dv += __shfl_xor_sync(0xffffffffu, dv, 2);
                if (tig == 0) {
                    int lrw = warp_m*32 + mt*16 + sel*8 + gid;
                    sh_s[warp_n][lrw] = sv;
                    sh_d[warp_n][lrw] = dv;
                }
            }
        __syncthreads();
        if (tid < 128) {
            g_s[row0 + tid] = sh_s[0][tid] + sh_s[1][tid];
            g_d[row0 + tid] = sh_d[0][tid] + sh_d[1][tid];
        }
    }
}

// ---------------- brute-force exact rank (replaces bitonic sort) -----------
// rank[i] = #{j : d_j < d_i  or  (d_j == d_i and j < i)}  -> scatter
__global__ __launch_bounds__(256) void rank_kernel()
{
    __shared__ float sh[NN];
    int b = blockIdx.y, tid = threadIdx.x;
    #pragma unroll
    for (int j = tid; j < NN; j += 256) sh[j] = g_d[b*NN + j];
    __syncthreads();
    int i = blockIdx.x * 64 + (tid >> 2);
    int q = tid & 3;
    float di = sh[i];
    int cnt = 0;
    int base = q * 512;
    #pragma unroll 8
    for (int t = 0; t < 512; t++) {
        int j = base + ((t + q*13) & 511);     // stagger to avoid bank conflicts
        float dj = sh[j];
        cnt += (dj < di) || (dj == di && j < i);
    }
    cnt += __shfl_xor_sync(0xffffffffu, cnt, 1);
    cnt += __shfl_xor_sync(0xffffffffu, cnt, 2);
    if (q == 0) {
        g_perm[b*NN + cnt] = i;
        g_sortedD[b*NN + cnt] = di;
    }
}

// ---------------- exp + suffix scan of sorted weights ----------------------
__global__ __launch_bounds__(1024) void scanE_kernel()
{
    __shared__ float sa[NN];
    __shared__ float sb[NN];
    int b = blockIdx.x, tid = threadIdx.x;
    #pragma unroll
    for (int j = tid; j < NN; j += 1024) sa[j] = g_sortedD[b*NN + j];
    __syncthreads();
    float dm = sa[NN-1];                      // ascending -> max at end
    for (int j = tid; j < NN; j += 1024) {
        float e = expf(sa[j] - dm);
        g_expD[b*NN + j] = e;
        sb[NN-1-j] = e;                        // reversed for suffix-as-prefix
    }
    __syncthreads();
    float* cur = sb; float* nxt = sa;
    for (int off = 1; off < NN; off <<= 1) {
        for (int j = tid; j < NN; j += 1024) {
            float v = cur[j];
            if (j >= off) v += cur[j-off];
            nxt[j] = v;
        }
        __syncthreads();
        float* tmp = cur; cur = nxt; nxt = tmp;
    }
    for (int j = tid; j < NN; j += 1024)
        g_sufE1[b*KTOT + j] = cur[NN-1-j];
    if (tid == 0) { g_sufE1[b*KTOT + NN] = 0.f; g_dmax[b] = dm; }
}

// ---------------- chunked vector prefix/suffix scans (both dirs fused) ------
__global__ __launch_bounds__(128) void scan_chunk_kernel()
{
    int ch = blockIdx.x, b = blockIdx.y;
    int f = threadIdx.x;
    int k0 = ch * CLEN;
    __shared__ int   rows[CLEN];
    __shared__ float wv[CLEN];
    if (f < CLEN) {
        rows[f] = g_perm[b*NN + k0 + f];
        wv[f]   = g_expD[b*NN + k0 + f];
    }
    __syncthreads();
    const float* hb = g_h1 + b*NN*FD;
    float v[CLEN];
    #pragma unroll
    for (int j = 0; j < CLEN; j++) v[j] = hb[rows[j]*FD + f];

    float acc = 0.f;
    #pragma unroll
    for (int j = 0; j < CLEN; j++) {
        g_preH[(b*KTOT + k0 + j)*FD + f] = acc;
        acc += v[j];
    }
    g_tot[((b*2+0)*NCH + ch)*FD + f] = acc;

    acc = 0.f;
    #pragma unroll
    for (int j = CLEN-1; j >= 0; j--) {
        acc += wv[j] * v[j];
        g_sufEH[(b*KTOT + k0 + j)*FD + f] = acc;
    }
    g_tot[((b*2+1)*NCH + ch)*FD + f] = acc;
}

// ---------------- fused: chunk-offset scan (blocks 0..7) + per-row scalars --
__global__ __launch_bounds__(128) void offsets_rows_kernel(
    const float* __restrict__ abp, int layer)
{
    int bx = blockIdx.x;
    if (bx < 2*BB) {
        int dir = bx & 1, b = bx >> 1;
        int f = threadIdx.x;
        if (dir == 0) {
            float acc = 0.f;
            #pragma unroll 8
            for (int c = 0; c < NCH; c++) {
                g_off[((b*2+0)*(NCH+1) + c)*FD + f] = acc;
                acc += g_tot[((b*2+0)*NCH + c)*FD + f];
            }
            g_off[((b*2+0)*(NCH+1) + NCH)*FD + f] = acc;
            g_preH[(b*KTOT + NN)*FD + f] = 0.f;
        } else {
            float acc = 0.f;
            #pragma unroll 8
            for (int c = NCH-1; c >= 0; c--) {
                g_off[((b*2+1)*(NCH+1) + c)*FD + f] = acc;
                acc += g_tot[((b*2+1)*NCH + c)*FD + f];
            }
            g_off[((b*2+1)*(NCH+1) + NCH)*FD + f] = 0.f;
            g_sufEH[(b*KTOT + NN)*FD + f] = 0.f;
        }
    } else {
        int row = (bx - 2*BB) * 128 + threadIdx.x;
        int b = row >> 11;
        float c   = g_s[row] + abp[layer];
        float thr = -c;
        const float* sd = g_sortedD + b*NN;
        int lo = 0, hi = NN;
        while (lo < hi) { int mid = (lo+hi) >> 1; if (sd[mid] <= thr) lo = mid+1; else hi = mid; }
        int k = lo;
        float E  = expf(c + g_dmax[b]);
        float di = g_d[row];
        float w  = (di > thr) ? expf(c + di) : 1.0f;
        float den = E * g_sufE1[b*KTOT + k] + (float)k - w;
        g_rk[row]   = k;
        g_rE[row]   = E;
        g_rw[row]   = w;
        g_rinv[row] = 1.0f / den;
    }
}

// ---------------- per-row combine (pure streaming) ---------------------------
// MODE 0: g = BN(relu(o + h2)) -> g_g     MODE 1: out = o + h2 -> d_out
template<int MODE>
__global__ __launch_bounds__(128) void combine_kernel(
    const float* __restrict__ gamma, const float* __restrict__ beta,
    const float* __restrict__ mean,  const float* __restrict__ var,
    float* __restrict__ out)
{
    int row = blockIdx.x;
    int b = row >> 11;
    int i = row & (NN-1);
    int f = threadIdx.x;
    int k      = g_rk[row];
    float E    = g_rE[row];
    float wown = g_rw[row];
    float inv  = g_rinv[row];
    int ch = k >> 4;
    float pre = g_preH [(b*KTOT + k)*FD + f] + g_off[((b*2+0)*(NCH+1) + ch)*FD + f];
    float suf = g_sufEH[(b*KTOT + k)*FD + f] + g_off[((b*2+1)*(NCH+1) + ch)*FD + f];
    float h1v = g_h1[row*FD + f];
    float o = (E*suf + pre - wown*h1v) * inv;
    float h2v = g_h2[row*FD + f];
    if (MODE == 0) {
        float gv = fmaxf(o + h2v, 0.f);
        float invs = rsqrtf(var[i] + 1e-5f);
        gv = (gv - mean[i]) * (invs * gamma[i]) + beta[i];
        g_g[row*FD + f] = gv;
    } else {
        out[row*FD + f] = o + h2v;
    }
}

// ---------------- orchestration ----------------
extern "C" void kernel_launch(void* const* d_in, const int* in_sizes, int n_in,
                              void* d_out, int out_size)
{
    (void)in_sizes; (void)n_in; (void)out_size;
    const float* x     = (const float*)d_in[0];
    const float* W1    = (const float*)d_in[2];
    const float* b1    = (const float*)d_in[3];
    const float* asrc  = (const float*)d_in[4];
    const float* adst  = (const float*)d_in[5];
    const float* ab    = (const float*)d_in[6];
    const float* gamma = (const float*)d_in[7];
    const float* beta  = (const float*)d_in[8];
    const float* mean  = (const float*)d_in[9];
    const float* var   = (const float*)d_in[10];
    float* out = (float*)d_out;

    for (int stage = 0; stage < 2; stage++) {
        int k = stage * 2;
        gemm_tf32_kernel<<<dim3(64, 2), 256>>>(x, stage, W1 + k*FD*FD, b1 + k*FD,
                                               asrc + k*FD, adst + k*FD);
        rank_kernel<<<dim3(NN/64, BB), 256>>>();
        scanE_kernel<<<BB, 1024>>>();
        scan_chunk_kernel<<<dim3(NCH, BB), 128>>>();
        offsets_rows_kernel<<<2*BB + MROWS/128, 128>>>(ab, k);
        if (stage == 0)
            combine_kernel<0><<<MROWS, 128>>>(gamma, beta, mean, var, out);
        else
            combine_kernel<1><<<MROWS, 128>>>(gamma, beta, mean, var, out);
    }
}

// round 12
// speedup vs baseline: 1.0467x; 1.0022x over previous
#include <cuda_runtime.h>
#include <math.h>

#define BB 4
#define NN 2048
#define FD 128
#define MROWS (BB*NN)     // 8192 rows total
#define KTOT (NN+1)       // 2049 prefix positions
#define NCH 128
#define CLEN 16           // NN / NCH

// ---------------- scratch (device globals; no allocation) ----------------
__device__ float g_h1[MROWS*FD];
__device__ float g_h2[MROWS*FD];
__device__ float g_g [MROWS*FD];
__device__ float g_s[MROWS];
__device__ float g_d[MROWS];
__device__ float g_sortedD[MROWS];
__device__ int   g_perm[MROWS];
__device__ float g_expD[MROWS];
__device__ float g_dmax[BB];
__device__ float g_sufE1[BB*KTOT];
__device__ float g_preH [BB*KTOT*FD];
__device__ float g_sufEH[BB*KTOT*FD];
__device__ float g_tot[BB*2*NCH*FD];
__device__ float g_off[BB*2*(NCH+1)*FD];
__device__ int   g_rk[MROWS];
__device__ float g_rE[MROWS];
__device__ float g_rw[MROWS];
__device__ float g_rinv[MROWS];

// ---------------- tf32 helpers ----------------
__device__ __forceinline__ float tf32_rn(float x) {
    unsigned u;
    asm("cvt.rna.tf32.f32 %0, %1;" : "=r"(u) : "f"(x));
    return __uint_as_float(u);
}

__device__ __forceinline__ void mma8(float* d, const float* a, float b0, float b1) {
    asm volatile(
        "mma.sync.aligned.m16n8k8.row.col.f32.tf32.tf32.f32 "
        "{%0,%1,%2,%3},{%4,%5,%6,%7},{%8,%9},{%0,%1,%2,%3};"
        : "+f"(d[0]), "+f"(d[1]), "+f"(d[2]), "+f"(d[3])
        : "r"(__float_as_uint(a[0])), "r"(__float_as_uint(a[1])),
          "r"(__float_as_uint(a[2])), "r"(__float_as_uint(a[3])),
          "r"(__float_as_uint(b0)),  "r"(__float_as_uint(b1)));
}

// ---------------- fused linear (3xTF32 mma) + fused s/d dot in epilogue -----
#define KC 16
__global__ __launch_bounds__(256) void gemm_tf32_kernel(
    const float* __restrict__ Xext, int useG,
    const float* __restrict__ W, const float* __restrict__ bias,
    const float* __restrict__ asrc, const float* __restrict__ adst)
{
    const float* __restrict__ X = useG ? g_g : Xext;
    __shared__ float Ah[128][KC+1], Al[128][KC+1];
    __shared__ float Bh[128][KC+1], Bl[128][KC+1];
    __shared__ float sh_s[2][128], sh_d[2][128];
    int tid = threadIdx.x;
    int wid = tid >> 5, lane = tid & 31;
    int gid = lane >> 2, tig = lane & 3;
    int warp_m = wid & 3;
    int warp_n = wid >> 2;
    int row0 = blockIdx.x * 128;
    int col0 = blockIdx.y * 128;

    float acc[2][8][4];
    #pragma unroll
    for (int mt = 0; mt < 2; mt++)
        #pragma unroll
        for (int nt = 0; nt < 8; nt++)
            #pragma unroll
            for (int q = 0; q < 4; q++) acc[mt][nt][q] = 0.f;

    int lrow = tid >> 2;          // 0..63
    int lq = (tid & 3) * 4;       // 0,4,8,12

    for (int kt = 0; kt < FD; kt += KC) {
        float4 xa = *(const float4*)(X + (row0+lrow   )*FD + kt + lq);
        float4 xb = *(const float4*)(X + (row0+lrow+64)*FD + kt + lq);
        float4 wa = *(const float4*)(W + (col0+lrow   )*FD + kt + lq);
        float4 wb = *(const float4*)(W + (col0+lrow+64)*FD + kt + lq);
        __syncthreads();
        {
            float v[4] = {xa.x, xa.y, xa.z, xa.w};
            #pragma unroll
            for (int c = 0; c < 4; c++) {
                float h = tf32_rn(v[c]);
                Ah[lrow][lq+c] = h; Al[lrow][lq+c] = tf32_rn(v[c] - h);
            }
        }
        {
            float v[4] = {xb.x, xb.y, xb.z, xb.w};
            #pragma unroll
            for (int c = 0; c < 4; c++) {
                float h = tf32_rn(v[c]);
                Ah[lrow+64][lq+c] = h; Al[lrow+64][lq+c] = tf32_rn(v[c] - h);
            }
        }
        {
            float v[4] = {wa.x, wa.y, wa.z, wa.w};
            #pragma unroll
            for (int c = 0; c < 4; c++) {
                float h = tf32_rn(v[c]);
                Bh[lrow][lq+c] = h; Bl[lrow][lq+c] = tf32_rn(v[c] - h);
            }
        }
        {
            float v[4] = {wb.x, wb.y, wb.z, wb.w};
            #pragma unroll
            for (int c = 0; c < 4; c++) {
                float h = tf32_rn(v[c]);
                Bh[lrow+64][lq+c] = h; Bl[lrow+64][lq+c] = tf32_rn(v[c] - h);
            }
        }
        __syncthreads();

        #pragma unroll
        for (int kk = 0; kk < KC; kk += 8) {
            float a_h[2][4], a_l[2][4];
            #pragma unroll
            for (int mt = 0; mt < 2; mt++) {
                int r = warp_m*32 + mt*16;
                a_h[mt][0] = Ah[r+gid  ][kk+tig];   a_h[mt][1] = Ah[r+gid+8][kk+tig];
                a_h[mt][2] = Ah[r+gid  ][kk+tig+4]; a_h[mt][3] = Ah[r+gid+8][kk+tig+4];
                a_l[mt][0] = Al[r+gid  ][kk+tig];   a_l[mt][1] = Al[r+gid+8][kk+tig];
                a_l[mt][2] = Al[r+gid  ][kk+tig+4]; a_l[mt][3] = Al[r+gid+8][kk+tig+4];
            }
            #pragma unroll
            for (int nt = 0; nt < 8; nt++) {
                int cc = warp_n*64 + nt*8 + gid;
                float bh0 = Bh[cc][kk+tig], bh1 = Bh[cc][kk+tig+4];
                float bl0 = Bl[cc][kk+tig], bl1 = Bl[cc][kk+tig+4];
                #pragma unroll
                for (int mt = 0; mt < 2; mt++) {
                    mma8(acc[mt][nt], a_h[mt], bh0, bh1);
                    mma8(acc[mt][nt], a_l[mt], bh0, bh1);
                    mma8(acc[mt][nt], a_h[mt], bl0, bl1);
                }
            }
        }
    }

    float* D = (blockIdx.y == 0) ? g_h1 : g_h2;
    float ps[2][2] = {{0.f,0.f},{0.f,0.f}};
    float pd[2][2] = {{0.f,0.f},{0.f,0.f}};
    #pragma unroll
    for (int mt = 0; mt < 2; mt++) {
        #pragma unroll
        for (int nt = 0; nt < 8; nt++) {
            int col = warp_n*64 + nt*8 + tig*2;
            float bv0 = bias[col0 + col];
            float bv1 = bias[col0 + col + 1];
            float v00 = acc[mt][nt][0]+bv0, v01 = acc[mt][nt][1]+bv1;
            float v10 = acc[mt][nt][2]+bv0, v11 = acc[mt][nt][3]+bv1;
            int r0 = row0 + warp_m*32 + mt*16 + gid;
            *(float2*)(D + r0*FD + col)     = make_float2(v00, v01);
            *(float2*)(D + (r0+8)*FD + col) = make_float2(v10, v11);
            if (blockIdx.y == 0) {
                float a0 = asrc[col], a1 = asrc[col+1];
                float d0 = adst[col], d1 = adst[col+1];
                ps[mt][0] += v00*a0 + v01*a1;  pd[mt][0] += v00*d0 + v01*d1;
                ps[mt][1] += v10*a0 + v11*a1;  pd[mt][1] += v10*d0 + v11*d1;
            }
        }
    }
    if (blockIdx.y == 0) {
        #pragma unroll
        for (int mt = 0; mt < 2; mt++)
            #pragma unroll
            for (int sel = 0; sel < 2; sel++) {
                float sv = ps[mt][sel], dv = pd[mt][sel];
                sv += __shfl_xor_sync(0xffffffffu, sv, 1);
                sv += __shfl_xor_sync(0xffffffffu, sv, 2);
                dv += __shfl_xor_sync(0xffffffffu, dv, 1);
                dv += __shfl_xor_sync(0xffffffffu, dv, 2);
                if (tig == 0) {
                    int lrw = warp_m*32 + mt*16 + sel*8 + gid;
                    sh_s[warp_n][lrw] = sv;
                    sh_d[warp_n][lrw] = dv;
                }
            }
        __syncthreads();
        if (tid < 128) {
            g_s[row0 + tid] = sh_s[0][tid] + sh_s[1][tid];
            g_d[row0 + tid] = sh_d[0][tid] + sh_d[1][tid];
        }
    }
}

// ---------------- brute-force exact rank (replaces bitonic sort) -----------
// rank[i] = #{j : d_j < d_i  or  (d_j == d_i and j < i)}  -> scatter
__global__ __launch_bounds__(256) void rank_kernel()
{
    __shared__ float sh[NN];
    int b = blockIdx.y, tid = threadIdx.x;
    #pragma unroll
    for (int j = tid; j < NN; j += 256) sh[j] = g_d[b*NN + j];
    __syncthreads();
    int i = blockIdx.x * 64 + (tid >> 2);
    int q = tid & 3;
    float di = sh[i];
    int cnt = 0;
    int base = q * 512;
    #pragma unroll 8
    for (int t = 0; t < 512; t++) {
        int j = base + ((t + q*13) & 511);     // stagger to avoid bank conflicts
        float dj = sh[j];
        cnt += (dj < di) || (dj == di && j < i);
    }
    cnt += __shfl_xor_sync(0xffffffffu, cnt, 1);
    cnt += __shfl_xor_sync(0xffffffffu, cnt, 2);
    if (q == 0) {
        g_perm[b*NN + cnt] = i;
        g_sortedD[b*NN + cnt] = di;
    }
}

// ---------------- exp + suffix scan of sorted weights ----------------------
__global__ __launch_bounds__(1024) void scanE_kernel()
{
    __shared__ float sa[NN];
    __shared__ float sb[NN];
    int b = blockIdx.x, tid = threadIdx.x;
    #pragma unroll
    for (int j = tid; j < NN; j += 1024) sa[j] = g_sortedD[b*NN + j];
    __syncthreads();
    float dm = sa[NN-1];                      // ascending -> max at end
    for (int j = tid; j < NN; j += 1024) {
        float e = expf(sa[j] - dm);
        g_expD[b*NN + j] = e;
        sb[NN-1-j] = e;                        // reversed for suffix-as-prefix
    }
    __syncthreads();
    float* cur = sb; float* nxt = sa;
    for (int off = 1; off < NN; off <<= 1) {
        for (int j = tid; j < NN; j += 1024) {
            float v = cur[j];
            if (j >= off) v += cur[j-off];
            nxt[j] = v;
        }
        __syncthreads();
        float* tmp = cur; cur = nxt; nxt = tmp;
    }
    for (int j = tid; j < NN; j += 1024)
        g_sufE1[b*KTOT + j] = cur[NN-1-j];
    if (tid == 0) { g_sufE1[b*KTOT + NN] = 0.f; g_dmax[b] = dm; }
}

// ---------------- chunked vector prefix/suffix scans (both dirs fused) ------
__global__ __launch_bounds__(128) void scan_chunk_kernel()
{
    int ch = blockIdx.x, b = blockIdx.y;
    int f = threadIdx.x;
    int k0 = ch * CLEN;
    __shared__ int   rows[CLEN];
    __shared__ float wv[CLEN];
    if (f < CLEN) {
        rows[f] = g_perm[b*NN + k0 + f];
        wv[f]   = g_expD[b*NN + k0 + f];
    }
    __syncthreads();
    const float* hb = g_h1 + b*NN*FD;
    float v[CLEN];
    #pragma unroll
    for (int j = 0; j < CLEN; j++) v[j] = hb[rows[j]*FD + f];

    float acc = 0.f;
    #pragma unroll
    for (int j = 0; j < CLEN; j++) {
        g_preH[(b*KTOT + k0 + j)*FD + f] = acc;
        acc += v[j];
    }
    g_tot[((b*2+0)*NCH + ch)*FD + f] = acc;

    acc = 0.f;
    #pragma unroll
    for (int j = CLEN-1; j >= 0; j--) {
        acc += wv[j] * v[j];
        g_sufEH[(b*KTOT + k0 + j)*FD + f] = acc;
    }
    g_tot[((b*2+1)*NCH + ch)*FD + f] = acc;
}

// ---------------- fused: chunk-offset scan (blocks 0..7) + per-row scalars --
__global__ __launch_bounds__(128) void offsets_rows_kernel(
    const float* __restrict__ abp, int layer)
{
    int bx = blockIdx.x;
    if (bx < 2*BB) {
        int dir = bx & 1, b = bx >> 1;
        int f = threadIdx.x;
        if (dir == 0) {
            float acc = 0.f;
            #pragma unroll 8
            for (int c = 0; c < NCH; c++) {
                g_off[((b*2+0)*(NCH+1) + c)*FD + f] = acc;
                acc += g_tot[((b*2+0)*NCH + c)*FD + f];
            }
            g_off[((b*2+0)*(NCH+1) + NCH)*FD + f] = acc;
            g_preH[(b*KTOT + NN)*FD + f] = 0.f;
        } else {
            float acc = 0.f;
            #pragma unroll 8
            for (int c = NCH-1; c >= 0; c--) {
                g_off[((b*2+1)*(NCH+1) + c)*FD + f] = acc;
                acc += g_tot[((b*2+1)*NCH + c)*FD + f];
            }
            g_off[((b*2+1)*(NCH+1) + NCH)*FD + f] = 0.f;
            g_sufEH[(b*KTOT + NN)*FD + f] = 0.f;
        }
    } else {
        int row = (bx - 2*BB) * 128 + threadIdx.x;
        int b = row >> 11;
        float c   = g_s[row] + abp[layer];
        float thr = -c;
        const float* sd = g_sortedD + b*NN;
        int lo = 0, hi = NN;
        while (lo < hi) { int mid = (lo+hi) >> 1; if (sd[mid] <= thr) lo = mid+1; else hi = mid; }
        int k = lo;
        float E  = expf(c + g_dmax[b]);
        float di = g_d[row];
        float w  = (di > thr) ? expf(c + di) : 1.0f;
        float den = E * g_sufE1[b*KTOT + k] + (float)k - w;
        g_rk[row]   = k;
        g_rE[row]   = E;
        g_rw[row]   = w;
        g_rinv[row] = 1.0f / den;
    }
}

// ---------------- per-row combine (pure streaming) ---------------------------
// MODE 0: g = BN(relu(o + h2)) -> g_g     MODE 1: out = o + h2 -> d_out
template<int MODE>
__global__ __launch_bounds__(128) void combine_kernel(
    const float* __restrict__ gamma, const float* __restrict__ beta,
    const float* __restrict__ mean,  const float* __restrict__ var,
    float* __restrict__ out)
{
    int row = blockIdx.x;
    int b = row >> 11;
    int i = row & (NN-1);
    int f = threadIdx.x;
    int k      = g_rk[row];
    float E    = g_rE[row];
    float wown = g_rw[row];
    float inv  = g_rinv[row];
    int ch = k >> 4;
    float pre = g_preH [(b*KTOT + k)*FD + f] + g_off[((b*2+0)*(NCH+1) + ch)*FD + f];
    float suf = g_sufEH[(b*KTOT + k)*FD + f] + g_off[((b*2+1)*(NCH+1) + ch)*FD + f];
    float h1v = g_h1[row*FD + f];
    float o = (E*suf + pre - wown*h1v) * inv;
    float h2v = g_h2[row*FD + f];
    if (MODE == 0) {
        float gv = fmaxf(o + h2v, 0.f);
        float invs = rsqrtf(var[i] + 1e-5f);
        gv = (gv - mean[i]) * (invs * gamma[i]) + beta[i];
        g_g[row*FD + f] = gv;
    } else {
        out[row*FD + f] = o + h2v;
    }
}

// ---------------- orchestration ----------------
extern "C" void kernel_launch(void* const* d_in, const int* in_sizes, int n_in,
                              void* d_out, int out_size)
{
    (void)in_sizes; (void)n_in; (void)out_size;
    const float* x     = (const float*)d_in[0];
    const float* W1    = (const float*)d_in[2];
    const float* b1    = (const float*)d_in[3];
    const float* asrc  = (const float*)d_in[4];
    const float* adst  = (const float*)d_in[5];
    const float* ab    = (const float*)d_in[6];
    const float* gamma = (const float*)d_in[7];
    const float* beta  = (const float*)d_in[8];
    const float* mean  = (const float*)d_in[9];
    const float* var   = (const float*)d_in[10];
    float* out = (float*)d_out;

    for (int stage = 0; stage < 2; stage++) {
        int k = stage * 2;
        gemm_tf32_kernel<<<dim3(64, 2), 256>>>(x, stage, W1 + k*FD*FD, b1 + k*FD,
                                               asrc + k*FD, adst + k*FD);
        rank_kernel<<<dim3(NN/64, BB), 256>>>();
        scanE_kernel<<<BB, 1024>>>();
        scan_chunk_kernel<<<dim3(NCH, BB), 128>>>();
        offsets_rows_kernel<<<2*BB + MROWS/128, 128>>>(ab, k);
        if (stage == 0)
            combine_kernel<0><<<MROWS, 128>>>(gamma, beta, mean, var, out);
        else
            combine_kernel<1><<<MROWS, 128>>>(gamma, beta, mean, var, out);
    }
}